// round 7
// baseline (speedup 1.0000x reference)
#include <cuda_runtime.h>
#include <cuda_bf16.h>
#include <cstdint>
#include <math.h>

#define NT 4096
#define ND 1024
#define NE 8
#define NF 2048
#define N2F 4096

#if defined(__CUDA_ARCH_FEAT_SM103_ALL) || defined(__CUDA_ARCH_FEAT_SM100_ALL)
#define TC_OK 1
#else
#define TC_OK 0
#endif

typedef unsigned long long ull;

// ---------------- scratch ----------------
__device__ int      g_cnt[NE];
__device__ int      g_tok[NE * NT];
__device__ float    g_wt[NT * 2];
__device__ int      g_slot[NT * 2];
__device__ int      g_eid[NT * 2];
__device__ uint32_t g_hidden_pk[(size_t)NE * NT * NF]; // bf16 hi|lo pack
__device__ float    g_y[(size_t)NE * NT * ND];

// ---------------- helpers ----------------
__device__ __forceinline__ uint32_t smem_u32(const void* p) {
    uint32_t a;
    asm("{ .reg .u64 t; cvta.to.shared.u64 t, %1; cvt.u32.u64 %0, t; }" : "=r"(a) : "l"(p));
    return a;
}
__device__ __forceinline__ uint32_t elect1() {
    uint32_t r;
    asm volatile("{ .reg .pred p; elect.sync _|p, 0xFFFFFFFF; selp.b32 %0,1,0,p; }" : "=r"(r));
    return r;
}
#define MBAR_INIT(a, c) asm volatile("mbarrier.init.shared.b64 [%0], %1;" :: "r"(a), "r"(c) : "memory")
#define MBAR_INVAL(a)   asm volatile("mbarrier.inval.shared.b64 [%0];" :: "r"(a) : "memory")
#define MBAR_WAIT(a, ph) do { uint32_t _m=(a); uint32_t _p=(ph); uint32_t _d;                               \
    asm volatile("{ .reg .pred p; mbarrier.try_wait.parity.acquire.cta.shared::cta.b64 p,[%1],%2; "        \
                 "selp.b32 %0,1,0,p; }" : "=r"(_d) : "r"(_m), "r"(_p) : "memory");                          \
    if (!_d) { asm volatile("{ .reg .pred P1; WL%=: "                                                      \
        "mbarrier.try_wait.parity.acquire.cta.shared::cta.b64 P1,[%0],%1,0x989680; "                       \
        "@P1 bra.uni WD%=; bra.uni WL%=; WD%=: }" :: "r"(_m), "r"(_p) : "memory"); } } while (0)
#define FENCE_ASYNC() asm volatile("fence.proxy.async.shared::cta;" ::: "memory")

#define SWZ(x) ((x) ^ (((x) >> 3) & 0x70))

#if TC_OK
#define TCG_ALLOC(sa, n)  asm volatile("tcgen05.alloc.cta_group::1.sync.aligned.shared::cta.b32 [%0], %1;" :: "r"(sa), "r"(n) : "memory")
#define TCG_DEALLOC(t, n) asm volatile("tcgen05.dealloc.cta_group::1.sync.aligned.b32 %0, %1;" :: "r"(t), "r"(n))
#define TCG_RELINQ()      asm volatile("tcgen05.relinquish_alloc_permit.cta_group::1.sync.aligned;")
#define TCG_COMMIT(a)     asm volatile("tcgen05.commit.cta_group::1.mbarrier::arrive::one.shared::cluster.b64 [%0];" :: "r"(a) : "memory")
#define TCG_FENCE_AFTER()  asm volatile("tcgen05.fence::after_thread_sync;" ::: "memory")
#define TCG_FENCE_BEFORE() asm volatile("tcgen05.fence::before_thread_sync;" ::: "memory")
#define TCG_WAIT_LD()      asm volatile("tcgen05.wait::ld.sync.aligned;" ::: "memory")

#define TCG_LD32(r, ta) \
    asm volatile("tcgen05.ld.sync.aligned.32x32b.x32.b32 " \
        "{%0,%1,%2,%3,%4,%5,%6,%7,%8,%9,%10,%11,%12,%13,%14,%15," \
        "%16,%17,%18,%19,%20,%21,%22,%23,%24,%25,%26,%27,%28,%29,%30,%31}, [%32];" \
        : "=r"((r)[0]),"=r"((r)[1]),"=r"((r)[2]),"=r"((r)[3]),"=r"((r)[4]),"=r"((r)[5]),"=r"((r)[6]),"=r"((r)[7]), \
          "=r"((r)[8]),"=r"((r)[9]),"=r"((r)[10]),"=r"((r)[11]),"=r"((r)[12]),"=r"((r)[13]),"=r"((r)[14]),"=r"((r)[15]), \
          "=r"((r)[16]),"=r"((r)[17]),"=r"((r)[18]),"=r"((r)[19]),"=r"((r)[20]),"=r"((r)[21]),"=r"((r)[22]),"=r"((r)[23]), \
          "=r"((r)[24]),"=r"((r)[25]),"=r"((r)[26]),"=r"((r)[27]),"=r"((r)[28]),"=r"((r)[29]),"=r"((r)[30]),"=r"((r)[31]) \
        : "r"(ta))

__device__ __forceinline__ uint64_t descK(uint32_t a) {   // K-major SW128: LBO=1, SBO=64
    return ((uint64_t)2 << 61) | ((uint64_t)1 << 46) | ((uint64_t)64 << 32) |
           ((uint64_t)1 << 16) | ((a >> 4) & 0x3FFF);
}
// kind::f16 idesc: dtype=F32, atype=btype=BF16, both K-major, N=64, M=128
#define IDESC_BF16 ((1u<<4) | (1u<<7) | (1u<<10) | (8u<<17) | (8u<<24))

__device__ __forceinline__ void mma_bf16(uint32_t d, uint64_t ad, uint64_t bd, uint32_t en) {
    asm volatile("{ .reg .pred p; setp.ne.u32 p, %4, 0;\n\t"
        "tcgen05.mma.cta_group::1.kind::f16 [%0], %1, %2, %3, {%5,%5,%5,%5}, p; }"
        :: "r"(d), "l"(ad), "l"(bd), "r"(IDESC_BF16), "r"(en), "r"(0u) : "memory");
}
#endif // TC_OK

__device__ __forceinline__ uint32_t bf2(float h, float l) {
    uint32_t r; asm("cvt.rn.bf16x2.f32 %0, %1, %2;" : "=r"(r) : "f"(h), "f"(l)); return r;
}
__device__ __forceinline__ void split8(float4 v0, float4 v1, uint4& hi, uint4& lo) {
    uint32_t u0 = __float_as_uint(v0.x), u1 = __float_as_uint(v0.y);
    uint32_t u2 = __float_as_uint(v0.z), u3 = __float_as_uint(v0.w);
    uint32_t u4 = __float_as_uint(v1.x), u5 = __float_as_uint(v1.y);
    uint32_t u6 = __float_as_uint(v1.z), u7 = __float_as_uint(v1.w);
    hi.x = __byte_perm(u0, u1, 0x7632); hi.y = __byte_perm(u2, u3, 0x7632);
    hi.z = __byte_perm(u4, u5, 0x7632); hi.w = __byte_perm(u6, u7, 0x7632);
    float l0 = v0.x - __uint_as_float(u0 & 0xffff0000u);
    float l1 = v0.y - __uint_as_float(u1 & 0xffff0000u);
    float l2 = v0.z - __uint_as_float(u2 & 0xffff0000u);
    float l3 = v0.w - __uint_as_float(u3 & 0xffff0000u);
    float l4 = v1.x - __uint_as_float(u4 & 0xffff0000u);
    float l5 = v1.y - __uint_as_float(u5 & 0xffff0000u);
    float l6 = v1.z - __uint_as_float(u6 & 0xffff0000u);
    float l7 = v1.w - __uint_as_float(u7 & 0xffff0000u);
    lo.x = bf2(l1, l0); lo.y = bf2(l3, l2); lo.z = bf2(l5, l4); lo.w = bf2(l7, l6);
}

// SMEM layout after 1024-aligned data0:
//   A: AHI @0 (16K), ALO @16K (16K)                      (32 KB, single buffer)
//   B: stage s @ 32768 + s*32768; BHI @+0 (16K: 2x8K subtiles), BLO @+16K
#define OFF_B    32768
#define DYNSMEM  99328

// ======================= zero counters =======================
__global__ void zero_cnt_kernel() {
    if (threadIdx.x < NE) g_cnt[threadIdx.x] = 0;
}

// ======================= router =======================
__global__ void router_kernel(const float* __restrict__ x,
                              const float* __restrict__ Wr,
                              const float* __restrict__ temp) {
    int t    = (blockIdx.x * blockDim.x + threadIdx.x) >> 5;
    int lane = threadIdx.x & 31;
    if (t >= NT) return;
    const float4* xr = (const float4*)(x + (size_t)t * ND);
    const float4* wr4 = (const float4*)Wr;
    float acc[NE];
#pragma unroll
    for (int e = 0; e < NE; e++) acc[e] = 0.f;
    for (int d4 = lane; d4 < ND / 4; d4 += 32) {
        float4 xv = xr[d4];
        float xs[4] = {xv.x, xv.y, xv.z, xv.w};
#pragma unroll
        for (int j = 0; j < 4; j++) {
            int d = 4 * d4 + j;
            float4 w0 = wr4[d * 2], w1 = wr4[d * 2 + 1];
            acc[0] = fmaf(xs[j], w0.x, acc[0]);
            acc[1] = fmaf(xs[j], w0.y, acc[1]);
            acc[2] = fmaf(xs[j], w0.z, acc[2]);
            acc[3] = fmaf(xs[j], w0.w, acc[3]);
            acc[4] = fmaf(xs[j], w1.x, acc[4]);
            acc[5] = fmaf(xs[j], w1.y, acc[5]);
            acc[6] = fmaf(xs[j], w1.z, acc[6]);
            acc[7] = fmaf(xs[j], w1.w, acc[7]);
        }
    }
#pragma unroll
    for (int e = 0; e < NE; e++) {
#pragma unroll
        for (int off = 16; off > 0; off >>= 1)
            acc[e] += __shfl_xor_sync(0xffffffffu, acc[e], off);
    }
    if (lane == 0) {
        float ti = 1.0f / temp[0];
#pragma unroll
        for (int e = 0; e < NE; e++) acc[e] *= ti;
        int i0 = 0; float l0 = acc[0];
#pragma unroll
        for (int e = 1; e < NE; e++) if (acc[e] > l0) { l0 = acc[e]; i0 = e; }
        int i1 = -1; float l1 = -3.4e38f;
#pragma unroll
        for (int e = 0; e < NE; e++)
            if (e != i0 && acc[e] > l1) { l1 = acc[e]; i1 = e; }
        float ex  = expf(l1 - l0);
        float w1v = ex / (1.f + ex);
        float w0v = 1.f - w1v;
        int p0 = atomicAdd(&g_cnt[i0], 1);
        int p1 = atomicAdd(&g_cnt[i1], 1);
        g_tok[i0 * NT + p0] = t;
        g_tok[i1 * NT + p1] = t;
        g_slot[2 * t]     = i0 * NT + p0;
        g_slot[2 * t + 1] = i1 * NT + p1;
        g_wt[2 * t]     = w0v;
        g_wt[2 * t + 1] = w1v;
        g_eid[2 * t]     = i0;
        g_eid[2 * t + 1] = i1;
    }
}

// ======================= tcgen05 GEMM1 + SwiGLU =======================
// M=128; N=128 (64 a-cols + paired 64 g-cols); K=1024, 16 chunks of 64. occ 2.
__global__ __launch_bounds__(256, 2) void gemm1_tc(
        const float* __restrict__ x,
        const float* __restrict__ W1,
        const float* __restrict__ b1) {
#if TC_OK
    int e    = blockIdx.z;
    int cnt  = g_cnt[e];
    int row0 = blockIdx.x * 128;
    if (row0 >= cnt) return;
    int na0 = blockIdx.y * 64;   // 64 a-cols (+ matching 64 g-cols)

    extern __shared__ char dynsmem[];
    uint32_t raw   = smem_u32(dynsmem);
    uint32_t base  = (raw + 1023) & ~1023u;
    uint32_t hdr   = base;
    uint32_t data0 = base + 1024;
    char* pdata = dynsmem + (data0 - raw);

    int tid = threadIdx.x, wid = tid >> 5, lane = tid & 31;

    if (tid == 0) { MBAR_INIT(hdr + 8, 1); MBAR_INIT(hdr + 16, 1); }
    if (wid == 0) { TCG_ALLOC(hdr, 128); TCG_RELINQ(); }
    __syncthreads();
    uint32_t tmem;
    asm("ld.shared.b32 %0, [%1];" : "=r"(tmem) : "r"(hdr));

    // A: thread handles (row = tid>>1, k-half kh = tid&1)
    int r0 = tid >> 1, kh = tid & 1;
    const float* ap;
    {
        int rr = row0 + r0; if (rr >= cnt) rr = cnt - 1;
        ap = x + (size_t)g_tok[e * NT + rr] * ND + kh * 32;
    }
    // B: thread handles column bc (0..127: 0-63 a, 64-127 g), k-half kh2
    int bc = tid & 127, kh2 = tid >> 7;
    int bnt = bc >> 6, bcc = bc & 63;
    const float* bcol = W1 + (size_t)e * ND * N2F +
        ((bc < 64) ? (size_t)(na0 + bc) : ((size_t)NF + na0 + (bc - 64)));

    const int CH = ND / 64; // 16
    for (int c = 0; c < CH; c++) {
        int b = c & 1;
        int k0 = c * 64;
        // 1. prefetch A into regs
        float4 av[8];
        {
            const float4* p = (const float4*)(ap + k0);
#pragma unroll
            for (int j = 0; j < 8; j++) av[j] = p[j];
        }
        // 2. B stage free (commit c-2)
        if (c >= 2) MBAR_WAIT(hdr + 8 + 8 * b, ((c - 2) >> 1) & 1);
        // 3. B fill (overlaps MMA(c-1))
        {
            char* sb = pdata + OFF_B + b * 32768;
            const float* gc = bcol + (size_t)(k0 + kh2 * 32) * N2F;
#pragma unroll
            for (int kb = 0; kb < 4; kb++) {
                float4 v0, v1;
                v0.x = gc[(size_t)(kb * 8 + 0) * N2F];
                v0.y = gc[(size_t)(kb * 8 + 1) * N2F];
                v0.z = gc[(size_t)(kb * 8 + 2) * N2F];
                v0.w = gc[(size_t)(kb * 8 + 3) * N2F];
                v1.x = gc[(size_t)(kb * 8 + 4) * N2F];
                v1.y = gc[(size_t)(kb * 8 + 5) * N2F];
                v1.z = gc[(size_t)(kb * 8 + 6) * N2F];
                v1.w = gc[(size_t)(kb * 8 + 7) * N2F];
                uint4 hi, lo; split8(v0, v1, hi, lo);
                uint32_t off = bnt * 8192 + SWZ((uint32_t)(bcc * 128 + kh2 * 64 + kb * 16));
                *(uint4*)(sb + off)         = hi;
                *(uint4*)(sb + 16384 + off) = lo;
            }
        }
        // 4. A buffer free (commit c-1, full drain)
        if (c >= 1) MBAR_WAIT(hdr + 8 + 8 * ((c - 1) & 1), ((c - 1) >> 1) & 1);
        // 5. A split + store
        {
            char* sa = pdata;
#pragma unroll
            for (int i = 0; i < 4; i++) {
                uint4 hi, lo; split8(av[2 * i], av[2 * i + 1], hi, lo);
                uint32_t off = SWZ((uint32_t)(r0 * 128 + kh * 64 + i * 16));
                *(uint4*)(sa + off)         = hi;
                *(uint4*)(sa + 16384 + off) = lo;
            }
        }
        FENCE_ASYNC();
        __syncthreads();
        // 6. 24 MMAs (3 passes x 4 ks x 2 nt)
        if (wid == 0 && elect1()) {
            uint32_t stB = data0 + OFF_B + b * 32768;
            uint64_t aHi = descK(data0), aLo = descK(data0 + 16384);
#pragma unroll
            for (int pi = 0; pi < 3; pi++) {
                uint32_t bPl = (pi == 1) ? 16384u : 0u;
                uint64_t ad0 = (pi == 2) ? aLo : aHi;
#pragma unroll
                for (int ks = 0; ks < 4; ks++) {
                    uint32_t en = (c > 0 || pi > 0 || ks > 0) ? 1u : 0u;
                    uint64_t ad = ad0 + (uint64_t)(ks * 2);
#pragma unroll
                    for (int nt = 0; nt < 2; nt++) {
                        uint64_t bd = descK(stB + bPl + nt * 8192) + (uint64_t)(ks * 2);
                        mma_bf16(tmem + nt * 64, ad, bd, en);
                    }
                }
            }
            TCG_COMMIT(hdr + 8 + 8 * b);
        }
    }
    MBAR_WAIT(hdr + 8 + 8 * ((CH - 1) & 1), ((CH - 1) >> 1) & 1);
    TCG_FENCE_AFTER();
    // epilogue: warp w -> subpartition w%4 rows, col half ch = w>>2
    int ch = wid >> 2;
    int row = row0 + (wid & 3) * 32 + lane;
    bool act = row < cnt;
    const float* b1a = b1 + (size_t)e * N2F + na0 + ch * 32;
    const float* b1g = b1 + (size_t)e * N2F + NF + na0 + ch * 32;
    {
        uint32_t ar[32], gr[32];
        TCG_LD32(ar, tmem + ch * 32);
        TCG_LD32(gr, tmem + 64 + ch * 32);
        TCG_WAIT_LD();
        if (act) {
            uint32_t pk[32];
#pragma unroll
            for (int q = 0; q < 32; q++) {
                float avv = __uint_as_float(ar[q]) + b1a[q];
                float gvv = __uint_as_float(gr[q]) + b1g[q];
                float hv = avv * (gvv / (1.f + __expf(-gvv)));
                uint32_t u = __float_as_uint(hv);
                float lof = hv - __uint_as_float(u & 0xffff0000u);
                uint16_t lob = __bfloat16_as_ushort(__float2bfloat16(lof));
                pk[q] = (u >> 16) | ((uint32_t)lob << 16);
            }
            uint32_t* dst = g_hidden_pk + ((size_t)e * NT + row) * NF + na0 + ch * 32;
#pragma unroll
            for (int q = 0; q < 8; q++) *(uint4*)(dst + 4 * q) = *(uint4*)&pk[4 * q];
        }
    }
    TCG_FENCE_BEFORE();
    __syncthreads();
    if (tid == 0) { MBAR_INVAL(hdr + 8); MBAR_INVAL(hdr + 16); }
    if (wid == 0) { TCG_DEALLOC(tmem, 128); }
#endif
}

// ======================= tcgen05 GEMM2 =======================
// M=128; N=128; K=2048, 32 chunks of 64. occ 2.
__global__ __launch_bounds__(256, 2) void gemm2_tc(const float* __restrict__ W2) {
#if TC_OK
    int e    = blockIdx.z;
    int cnt  = g_cnt[e];
    int row0 = blockIdx.x * 128;
    if (row0 >= cnt) return;
    int n0 = blockIdx.y * 128;

    extern __shared__ char dynsmem[];
    uint32_t raw   = smem_u32(dynsmem);
    uint32_t base  = (raw + 1023) & ~1023u;
    uint32_t hdr   = base;
    uint32_t data0 = base + 1024;
    char* pdata = dynsmem + (data0 - raw);

    int tid = threadIdx.x, wid = tid >> 5, lane = tid & 31;

    if (tid == 0) { MBAR_INIT(hdr + 8, 1); MBAR_INIT(hdr + 16, 1); }
    if (wid == 0) { TCG_ALLOC(hdr, 128); TCG_RELINQ(); }
    __syncthreads();
    uint32_t tmem;
    asm("ld.shared.b32 %0, [%1];" : "=r"(tmem) : "r"(hdr));

    int r0 = tid >> 1, kh = tid & 1;
    const uint32_t* hp;
    {
        int rr = row0 + r0; if (rr >= cnt) rr = cnt - 1;
        hp = g_hidden_pk + ((size_t)e * NT + rr) * NF + kh * 32;
    }
    int bc = tid & 127, kh2 = tid >> 7;
    int bnt = bc >> 6, bcc = bc & 63;
    const float* bcol = W2 + (size_t)e * NF * ND + n0 + bc;

    const int CH = NF / 64; // 32
    for (int c = 0; c < CH; c++) {
        int b = c & 1;
        int k0 = c * 64;
        // 1. prefetch A (packed hidden)
        uint4 aw[8];
        {
            const uint4* p = (const uint4*)(hp + k0);
#pragma unroll
            for (int j = 0; j < 8; j++) aw[j] = p[j];
        }
        // 2. B stage free
        if (c >= 2) MBAR_WAIT(hdr + 8 + 8 * b, ((c - 2) >> 1) & 1);
        // 3. B fill
        {
            char* sb = pdata + OFF_B + b * 32768;
            const float* gc = bcol + (size_t)(k0 + kh2 * 32) * ND;
#pragma unroll
            for (int kb = 0; kb < 4; kb++) {
                float4 v0, v1;
                v0.x = gc[(size_t)(kb * 8 + 0) * ND];
                v0.y = gc[(size_t)(kb * 8 + 1) * ND];
                v0.z = gc[(size_t)(kb * 8 + 2) * ND];
                v0.w = gc[(size_t)(kb * 8 + 3) * ND];
                v1.x = gc[(size_t)(kb * 8 + 4) * ND];
                v1.y = gc[(size_t)(kb * 8 + 5) * ND];
                v1.z = gc[(size_t)(kb * 8 + 6) * ND];
                v1.w = gc[(size_t)(kb * 8 + 7) * ND];
                uint4 hi, lo; split8(v0, v1, hi, lo);
                uint32_t off = bnt * 8192 + SWZ((uint32_t)(bcc * 128 + kh2 * 64 + kb * 16));
                *(uint4*)(sb + off)         = hi;
                *(uint4*)(sb + 16384 + off) = lo;
            }
        }
        // 4. A buffer free
        if (c >= 1) MBAR_WAIT(hdr + 8 + 8 * ((c - 1) & 1), ((c - 1) >> 1) & 1);
        // 5. A unpack + store
        {
            char* sa = pdata;
#pragma unroll
            for (int i = 0; i < 4; i++) {
                uint4 w0 = aw[2 * i], w1 = aw[2 * i + 1];
                uint4 hi, lo;
                hi.x = __byte_perm(w0.x, w0.y, 0x5410); lo.x = __byte_perm(w0.x, w0.y, 0x7632);
                hi.y = __byte_perm(w0.z, w0.w, 0x5410); lo.y = __byte_perm(w0.z, w0.w, 0x7632);
                hi.z = __byte_perm(w1.x, w1.y, 0x5410); lo.z = __byte_perm(w1.x, w1.y, 0x7632);
                hi.w = __byte_perm(w1.z, w1.w, 0x5410); lo.w = __byte_perm(w1.z, w1.w, 0x7632);
                uint32_t off = SWZ((uint32_t)(r0 * 128 + kh * 64 + i * 16));
                *(uint4*)(sa + off)         = hi;
                *(uint4*)(sa + 16384 + off) = lo;
            }
        }
        FENCE_ASYNC();
        __syncthreads();
        if (wid == 0 && elect1()) {
            uint32_t stB = data0 + OFF_B + b * 32768;
            uint64_t aHi = descK(data0), aLo = descK(data0 + 16384);
#pragma unroll
            for (int pi = 0; pi < 3; pi++) {
                uint32_t bPl = (pi == 1) ? 16384u : 0u;
                uint64_t ad0 = (pi == 2) ? aLo : aHi;
#pragma unroll
                for (int ks = 0; ks < 4; ks++) {
                    uint32_t en = (c > 0 || pi > 0 || ks > 0) ? 1u : 0u;
                    uint64_t ad = ad0 + (uint64_t)(ks * 2);
#pragma unroll
                    for (int nt = 0; nt < 2; nt++) {
                        uint64_t bd = descK(stB + bPl + nt * 8192) + (uint64_t)(ks * 2);
                        mma_bf16(tmem + nt * 64, ad, bd, en);
                    }
                }
            }
            TCG_COMMIT(hdr + 8 + 8 * b);
        }
    }
    MBAR_WAIT(hdr + 8 + 8 * ((CH - 1) & 1), ((CH - 1) >> 1) & 1);
    TCG_FENCE_AFTER();
    int ch = wid >> 2;
    int row = row0 + (wid & 3) * 32 + lane;
    bool act = row < cnt;
    for (int j = ch * 2; j < ch * 2 + 2; j++) {
        uint32_t yr[32];
        TCG_LD32(yr, tmem + j * 32);
        TCG_WAIT_LD();
        if (act) {
            float* dst = g_y + ((size_t)e * NT + row) * ND + n0 + j * 32;
#pragma unroll
            for (int q = 0; q < 8; q++) *(uint4*)(dst + 4 * q) = *(uint4*)&yr[4 * q];
        }
    }
    TCG_FENCE_BEFORE();
    __syncthreads();
    if (tid == 0) { MBAR_INVAL(hdr + 8); MBAR_INVAL(hdr + 16); }
    if (wid == 0) { TCG_DEALLOC(tmem, 128); }
#endif
}

// ======================= combine =======================
__global__ void combine_kernel(const float* __restrict__ b2, float* __restrict__ out) {
    int t = blockIdx.x;
    float w0 = g_wt[2 * t], w1 = g_wt[2 * t + 1];
    int s0 = g_slot[2 * t], s1 = g_slot[2 * t + 1];
    int e0 = g_eid[2 * t],  e1 = g_eid[2 * t + 1];
    int c = threadIdx.x * 4;
    float4 y0  = *(const float4*)(g_y + (size_t)s0 * ND + c);
    float4 y1  = *(const float4*)(g_y + (size_t)s1 * ND + c);
    float4 bb0 = *(const float4*)(b2 + (size_t)e0 * ND + c);
    float4 bb1 = *(const float4*)(b2 + (size_t)e1 * ND + c);
    float4 o;
    o.x = w0 * (y0.x + bb0.x) + w1 * (y1.x + bb1.x);
    o.y = w0 * (y0.y + bb0.y) + w1 * (y1.y + bb1.y);
    o.z = w0 * (y0.z + bb0.z) + w1 * (y1.z + bb1.z);
    o.w = w0 * (y0.w + bb0.w) + w1 * (y1.w + bb1.w);
    *(float4*)(out + (size_t)t * ND + c) = o;
}

// ======================= launch =======================
extern "C" void kernel_launch(void* const* d_in, const int* in_sizes, int n_in,
                              void* d_out, int out_size) {
    const float* x    = (const float*)d_in[0];
    const float* Wr   = (const float*)d_in[1];
    const float* temp = (const float*)d_in[2];
    const float* W1   = (const float*)d_in[3];
    const float* b1   = (const float*)d_in[4];
    const float* W2   = (const float*)d_in[5];
    const float* b2   = (const float*)d_in[6];
    float* out = (float*)d_out;

    cudaFuncSetAttribute(gemm1_tc, cudaFuncAttributeMaxDynamicSharedMemorySize, DYNSMEM);
    cudaFuncSetAttribute(gemm2_tc, cudaFuncAttributeMaxDynamicSharedMemorySize, DYNSMEM);

    zero_cnt_kernel<<<1, 32>>>();
    router_kernel<<<NT / 8, 256>>>(x, Wr, temp);
    gemm1_tc<<<dim3(NT / 128, NF / 64, NE), 256, DYNSMEM>>>(x, W1, b1);
    gemm2_tc<<<dim3(NT / 128, ND / 128, NE), 256, DYNSMEM>>>(W2);
    combine_kernel<<<NT, 256>>>(b2, out);
}